// round 7
// baseline (speedup 1.0000x reference)
#include <cuda_runtime.h>
#include <cuda_bf16.h>
#include <cstdint>

#define B_ 4
#define N_ 8192
#define C_ 64
#define K_ 16
#define O_ 128

#define CH 4                       // candidate chunks per query
#define QT 128                     // threads = queries per CTA
#define CTILE 64                   // candidates per smem tile
#define CCHUNK (N_ / CH)           // 2048
#define NTILES (CCHUNK / CTILE)    // 32

// ---------------- scratch (no allocs allowed) ----------------
__device__ __align__(16) float g_feats[B_ * N_ * C_];
__device__ __align__(16) float g_xx[B_ * N_];
__device__ __align__(16) int   g_knn[B_ * N_ * K_];
__device__ __align__(16) float g_pval[B_ * CH * N_ * K_];   // partial top-16 values
__device__ __align__(16) int   g_pidx[B_ * CH * N_ * K_];   // partial top-16 indices

typedef unsigned long long u64;

// ---------------- packed f32x2 helpers (sm_103a) ----------------
__device__ __forceinline__ u64 fma2(u64 a, u64 b, u64 c) {
    u64 d;
    asm("fma.rn.f32x2 %0, %1, %2, %3;" : "=l"(d) : "l"(a), "l"(b), "l"(c));
    return d;
}
__device__ __forceinline__ u64 add2(u64 a, u64 b) {
    u64 d;
    asm("add.rn.f32x2 %0, %1, %2;" : "=l"(d) : "l"(a), "l"(b));
    return d;
}
__device__ __forceinline__ float psum(u64 v) {
    return __uint_as_float((unsigned)v) + __uint_as_float((unsigned)(v >> 32));
}
__device__ __forceinline__ uint32_t smem_u32(const void* p) {
    uint32_t a;
    asm("{ .reg .u64 t; cvta.to.shared.u64 t, %1; cvt.u32.u64 %0, t; }" : "=r"(a) : "l"(p));
    return a;
}
__device__ __forceinline__ void cp_async16(uint32_t dst, const void* src) {
    asm volatile("cp.async.cg.shared.global [%0], [%1], 16;" :: "r"(dst), "l"(src) : "memory");
}
__device__ __forceinline__ void cp_commit() {
    asm volatile("cp.async.commit_group;" ::: "memory");
}
__device__ __forceinline__ void cp_wait1() {
    asm volatile("cp.async.wait_group 1;" ::: "memory");
}
__device__ __forceinline__ void cp_wait0() {
    asm volatile("cp.async.wait_group 0;" ::: "memory");
}

// ---------------- kernel 1: transpose x -> feats, compute ||x||^2 ----------------
__global__ void __launch_bounds__(256) prep_kernel(const float* __restrict__ x) {
    int idx = blockIdx.x * 256 + threadIdx.x;      // 0 .. B*N-1
    int b = idx >> 13;
    int n = idx & (N_ - 1);
    const float* xb = x + (size_t)b * C_ * N_ + n;
    float v[C_];
    float acc = 0.f;
#pragma unroll
    for (int c = 0; c < C_; ++c) {
        float t = xb[(size_t)c * N_];              // coalesced across threads
        v[c] = t;
        acc = fmaf(t, t, acc);
    }
    float4* fp = reinterpret_cast<float4*>(g_feats + (size_t)idx * C_);
#pragma unroll
    for (int i = 0; i < C_ / 4; ++i)
        fp[i] = make_float4(v[4 * i], v[4 * i + 1], v[4 * i + 2], v[4 * i + 3]);
    g_xx[idx] = acc;
}

// ---------------- kernel 2: exact fp32 KNN, spill-free FFMA2 core ----------------
// Grid (64, CH, B_): 128 queries x CCHUNK candidates per CTA, occupancy 3.
// smem layout (bytes):
#define KS_TILE 0                         // 2 x 16384 candidate tiles
#define KS_CXX  32768                     // 2 x 64 floats
#define KS_MV   33280                     // 128 x 16 fp32
#define KS_MI   41472                     // 128 x 16 int
#define KNN_SMEM 49664

__global__ void __launch_bounds__(QT, 3) knn_kernel() {
    extern __shared__ char smem[];
    uint32_t sb = smem_u32(smem);
    const int t = threadIdx.x;
    const int b = blockIdx.z;
    const int ch = blockIdx.y;
    const int q = blockIdx.x * QT + t;
    const int c0 = ch * CCHUNK;

    const float* fb = g_feats + (size_t)b * N_ * C_;
    const float* xxb = g_xx + b * N_;

    float* s_cxx = reinterpret_cast<float*>(smem + KS_CXX);
    float* mv = reinterpret_cast<float*>(smem + KS_MV) + t * 16;
    int*   mi = reinterpret_cast<int*>(smem + KS_MI) + t * 16;

    // query row in registers (64 regs)
    u64 qv[32];
    {
        const u64* qp = reinterpret_cast<const u64*>(fb + (size_t)q * C_);
#pragma unroll
        for (int i = 0; i < 32; ++i) qv[i] = qp[i];
    }
    const float qxx = xxb[q];
#pragma unroll
    for (int i = 0; i < 16; ++i) { mv[i] = -3.4e38f; mi[i] = 0; }
    float thr = -3.4e38f;

    // cp.async tile loader: 64 rows x 256 B = 1024 x 16B chunks, 8 per thread
    auto issue = [&](int tile, int buf) {
        const char* src = reinterpret_cast<const char*>(fb + (size_t)(c0 + tile * CTILE) * C_);
        uint32_t dst = sb + KS_TILE + buf * 16384;
#pragma unroll
        for (int i = 0; i < 8; ++i) {
            int chunk = t + i * QT;
            cp_async16(dst + chunk * 16, src + (size_t)chunk * 16);
        }
        cp_commit();
        if (t < CTILE) s_cxx[buf * CTILE + t] = xxb[c0 + tile * CTILE + t];
    };
    issue(0, 0);

    for (int tile = 0; tile < NTILES; ++tile) {
        const int buf = tile & 1;
        if (tile + 1 < NTILES) { issue(tile + 1, buf ^ 1); cp_wait1(); }
        else                   { cp_wait0(); }
        __syncthreads();                    // tile + cxx visible

        const ulonglong2* tb = reinterpret_cast<const ulonglong2*>(smem + KS_TILE + buf * 16384);
        const float* cx = s_cxx + buf * CTILE;
        const int cbase = c0 + tile * CTILE;

#pragma unroll 1
        for (int jb = 0; jb < CTILE / 8; ++jb) {
            const int j0 = jb * 8;
            const ulonglong2* rows = tb + j0 * 16;    // 8 rows x 16 u2 each

            // 8 independent accumulation chains (branch-free FFMA2 stream)
            u64 acc[8];
#pragma unroll
            for (int c = 0; c < 8; ++c) acc[c] = 0;
#pragma unroll
            for (int i = 0; i < 16; ++i) {
#pragma unroll
                for (int c = 0; c < 8; ++c) {
                    ulonglong2 u = rows[c * 16 + i];   // broadcast LDS.128
                    acc[c] = fma2(qv[2 * i + 1], u.y, fma2(qv[2 * i], u.x, acc[c]));
                }
            }

            float d[8];
            float dmax = -3.4e38f;
#pragma unroll
            for (int c = 0; c < 8; ++c) {
                float s = psum(acc[c]);
                float qc = qxx + cx[j0 + c];
                d[c] = fmaf(2.f, s, -qc);              // exact fp32 neg sq dist
                dmax = fmaxf(dmax, d[c]);
            }

            if (dmax > thr) {                          // one divergence region per 8 candidates
#pragma unroll
                for (int c = 0; c < 8; ++c) {
                    float dv = d[c];
                    if (dv > thr) {
                        int jj = cbase + j0 + c;
                        int p = 15;
                        while (p > 0 && mv[p - 1] < dv) {   // ties keep earlier (lower) index
                            mv[p] = mv[p - 1];
                            mi[p] = mi[p - 1];
                            --p;
                        }
                        mv[p] = dv;
                        mi[p] = jj;
                        thr = mv[15];
                    }
                }
            }
        }
        __syncthreads();                    // done with buf before overwrite
    }

    float* pv = g_pval + (((size_t)(b * CH + ch)) * N_ + q) * 16;
    int*   pi = g_pidx + (((size_t)(b * CH + ch)) * N_ + q) * 16;
#pragma unroll
    for (int i = 0; i < 16; ++i) { pv[i] = mv[i]; pi[i] = mi[i]; }
}

// ---------------- kernel 2b: CH-way merge of partial top-16 lists ----------------
__global__ void __launch_bounds__(256) merge_kernel() {
    int id = blockIdx.x * 256 + threadIdx.x;       // 0 .. B*N-1
    int b = id >> 13;
    int q = id & (N_ - 1);

    const float* pv[CH];
    const int*   pi[CH];
    float hv[CH];
    int   hx[CH];
    int   cur[CH];
#pragma unroll
    for (int c = 0; c < CH; ++c) {
        pv[c] = g_pval + (((size_t)(b * CH + c)) * N_ + q) * 16;
        pi[c] = g_pidx + (((size_t)(b * CH + c)) * N_ + q) * 16;
        hv[c] = pv[c][0];
        hx[c] = pi[c][0];
        cur[c] = 0;
    }
    int* og = g_knn + (size_t)id * K_;
#pragma unroll
    for (int s = 0; s < 16; ++s) {
        int best = 0;
#pragma unroll
        for (int c = 1; c < CH; ++c)
            if (hv[c] > hv[best] || (hv[c] == hv[best] && hx[c] < hx[best])) best = c;
        og[s] = hx[best];
        if (++cur[best] < 16) {
            hv[best] = pv[best][cur[best]];
            hx[best] = pi[best][cur[best]];
        } else {
            hv[best] = -3.4e38f;
            hx[best] = 0x7fffffff;
        }
    }
}

// ---------------- kernel 3: edge conv + max pool ----------------
#define CT  128   // threads = output channels
#define PPB 64    // points per block

__device__ __forceinline__ void cv_issue(const float* fb, const int* s_nidx,
                                         int p0, int pl, int t,
                                         float4* rn, float4* rx) {
#pragma unroll
    for (int s = 0; s < 3; ++s) {
        if (s == 2 && t >= 16) continue;
        int cid = t + s * CT;
        int r = cid >> 4, c4 = cid & 15;
        const float4* xrow = reinterpret_cast<const float4*>(fb + (size_t)(p0 + pl) * C_);
        if (r < 16) {
            int nj = s_nidx[pl * K_ + r];
            rn[s] = reinterpret_cast<const float4*>(fb + (size_t)nj * C_)[c4];
            rx[s] = xrow[c4];
        } else {
            rn[s] = xrow[c4];
        }
    }
}

__device__ __forceinline__ void cv_commit(float4* buf, int t,
                                          const float4* rn, const float4* rx) {
#pragma unroll
    for (int s = 0; s < 3; ++s) {
        if (s == 2 && t >= 16) continue;
        int cid = t + s * CT;
        int r = cid >> 4, c4 = cid & 15;
        float4 v = rn[s];
        if (r < 16) { v.x -= rx[s].x; v.y -= rx[s].y; v.z -= rx[s].z; v.w -= rx[s].w; }
        buf[r * 16 + c4] = v;
    }
}

__global__ void __launch_bounds__(CT) conv_kernel(const float* __restrict__ W,
                                                  const float* __restrict__ bias,
                                                  float* __restrict__ out) {
    __shared__ float4 sbuf[2][17 * 16];
    __shared__ int s_nidx[PPB * K_];

    int b = blockIdx.y;
    int p0 = blockIdx.x * PPB;
    int t = threadIdx.x;
    const float* fb = g_feats + (size_t)b * N_ * C_;

    u64 w2[64];
    {
        const u64* wp = reinterpret_cast<const u64*>(W + (size_t)t * 2 * C_);
#pragma unroll
        for (int i = 0; i < 64; ++i) w2[i] = wp[i];
    }
    float bo = bias[t];

    for (int i = t; i < PPB * K_; i += CT)
        s_nidx[i] = g_knn[(size_t)(b * N_ + p0) * K_ + i];
    __syncthreads();

    float4 rn[3], rx[3];
    cv_issue(fb, s_nidx, p0, 0, t, rn, rx);

    for (int pl = 0; pl < PPB; ++pl) {
        float4* buf = sbuf[pl & 1];
        cv_commit(buf, t, rn, rx);
        __syncthreads();
        if (pl + 1 < PPB) cv_issue(fb, s_nidx, p0, pl + 1, t, rn, rx);

        const ulonglong2* base = reinterpret_cast<const ulonglong2*>(buf);

        u64 a0 = 0, a1 = 0;
#pragma unroll
        for (int i = 0; i < 16; ++i) {
            ulonglong2 u = base[16 * 16 + i];
            a0 = fma2(w2[2 * i], u.x, a0);
            a1 = fma2(w2[2 * i + 1], u.y, a1);
        }
        float aterm = psum(add2(a0, a1));

        float m = -3.4e38f;
#pragma unroll
        for (int k = 0; k < 16; ++k) {
            // 4 independent fma2 chains for ILP (pipe-saturating at low occ)
            u64 c0 = 0, c1 = 0, c2 = 0, c3 = 0;
#pragma unroll
            for (int i = 0; i < 8; ++i) {
                ulonglong2 u = base[k * 16 + i];
                ulonglong2 v = base[k * 16 + 8 + i];
                c0 = fma2(w2[32 + 2 * i], u.x, c0);
                c1 = fma2(w2[33 + 2 * i], u.y, c1);
                c2 = fma2(w2[48 + 2 * i], v.x, c2);
                c3 = fma2(w2[49 + 2 * i], v.y, c3);
            }
            float tk = psum(add2(add2(c0, c1), add2(c2, c3)));
            m = fmaxf(m, tk);
        }

        out[(size_t)(b * O_ + t) * N_ + p0 + pl] = aterm + m + bo;
    }
}

// ---------------- launch ----------------
extern "C" void kernel_launch(void* const* d_in, const int* in_sizes, int n_in,
                              void* d_out, int out_size) {
    (void)in_sizes; (void)n_in; (void)out_size;
    const float* x    = (const float*)d_in[0];   // (4, 64, 8192, 1)
    const float* W    = (const float*)d_in[1];   // (128, 128)
    const float* bias = (const float*)d_in[2];   // (128,)
    float* out = (float*)d_out;                  // (4, 128, 8192, 1)

    cudaFuncSetAttribute(knn_kernel, cudaFuncAttributeMaxDynamicSharedMemorySize, KNN_SMEM);

    prep_kernel<<<(B_ * N_) / 256, 256>>>(x);
    knn_kernel<<<dim3(N_ / QT, CH, B_), QT, KNN_SMEM>>>();
    merge_kernel<<<(B_ * N_) / 256, 256>>>();
    conv_kernel<<<dim3(N_ / PPB, B_), CT>>>(W, bias, out);
}